// round 2
// baseline (speedup 1.0000x reference)
#include <cuda_runtime.h>

// FWHT, 4096 rows x 16384 fp32. One CTA per row, 512 threads, 32 elems/thread.
// 3 register phases (H32 over bits 13..9, H32 over bits 8..4, H16 over bits 3..0)
// with 2 bank-conflict-free shared-memory exchanges.

#define N_ELEM 16384
#define THREADS 512
// max swzB index = 20*1023 + 15 + 16*31 = 20971 -> round up to 20992
#define SMEM_FLOATS 20992

// Exchange-1 swizzle: pad 16 floats per 512-float segment.
__device__ __forceinline__ int swzA(int i) { return i + ((i >> 9) << 4); }
// Exchange-2 swizzle: pad 4 per 16-float group + 16 per 512-float segment
// (cumulative, so it is injective: segment s maps to [656s, 656s+635]).
__device__ __forceinline__ int swzB(int i) {
    return i + ((i >> 4) << 2) + ((i >> 9) << 4);
}

template <int N>
__device__ __forceinline__ void hadN(float* v) {
#pragma unroll
    for (int s = 1; s < N; s <<= 1) {
#pragma unroll
        for (int i = 0; i < N; i++) {
            if ((i & s) == 0) {
                float a = v[i];
                float b = v[i | s];
                v[i]     = a + b;
                v[i | s] = a - b;
            }
        }
    }
}

__global__ __launch_bounds__(THREADS, 2)
void fwht_kernel(const float* __restrict__ in, float* __restrict__ out) {
    extern __shared__ float sh[];
    const int t = threadIdx.x;
    const size_t row = (size_t)blockIdx.x * N_ELEM;
    const float* __restrict__ pin = in + row;

    float v[32];

    // ---- Phase 1: idx = t + 512*j  (regs cover bits 13..9), coalesced loads
#pragma unroll
    for (int j = 0; j < 32; j++) v[j] = pin[t + (j << 9)];
    hadN<32>(v);

#pragma unroll
    for (int j = 0; j < 32; j++) sh[swzA(t + (j << 9))] = v[j];
    __syncthreads();

    // ---- Phase 2: idx = (t&15) + 16*j + 512*(t>>4)  (regs cover bits 8..4)
    const int base2 = (t & 15) + ((t >> 4) << 9);
#pragma unroll
    for (int j = 0; j < 32; j++) v[j] = sh[swzA(base2 + (j << 4))];
    hadN<32>(v);
    __syncthreads();  // WAR: everyone done reading layout A before writing layout B
#pragma unroll
    for (int j = 0; j < 32; j++) sh[swzB(base2 + (j << 4))] = v[j];
    __syncthreads();

    // ---- Phase 3: idx = (g<<13) + (t<<4) + j  (regs cover bits 3..0), 2 groups
    float* __restrict__ pout = out + row;
#pragma unroll
    for (int g = 0; g < 2; g++) {
        const int base3 = (g << 13) + (t << 4);
        float w[16];
        // 16-float group is contiguous & 16B-aligned in swizzled space
        const float4* p4 = reinterpret_cast<const float4*>(&sh[swzB(base3)]);
#pragma unroll
        for (int k = 0; k < 4; k++) {
            float4 f = p4[k];
            w[4 * k + 0] = f.x;
            w[4 * k + 1] = f.y;
            w[4 * k + 2] = f.z;
            w[4 * k + 3] = f.w;
        }
        hadN<16>(w);
        // scale by 2^(-14/2) = 1/128 and store coalesced (STG.128)
        float4* q4 = reinterpret_cast<float4*>(&pout[base3]);
#pragma unroll
        for (int k = 0; k < 4; k++) {
            float4 f;
            f.x = w[4 * k + 0] * 0.0078125f;
            f.y = w[4 * k + 1] * 0.0078125f;
            f.z = w[4 * k + 2] * 0.0078125f;
            f.w = w[4 * k + 3] * 0.0078125f;
            q4[k] = f;
        }
    }
}

extern "C" void kernel_launch(void* const* d_in, const int* in_sizes, int n_in,
                              void* d_out, int out_size) {
    const float* phi = (const float*)d_in[0];
    float* out = (float*)d_out;

    const size_t smem = SMEM_FLOATS * sizeof(float);  // 83968 B > 48K default
    cudaFuncSetAttribute(fwht_kernel,
                         cudaFuncAttributeMaxDynamicSharedMemorySize,
                         (int)smem);

    const int batch = in_sizes[0] / N_ELEM;  // 4096
    fwht_kernel<<<batch, THREADS, smem>>>(phi, out);
}

// round 3
// speedup vs baseline: 1.1480x; 1.1480x over previous
#include <cuda_runtime.h>

// FWHT, 4096 rows x 16384 fp32. One CTA per row, 1024 threads, 16 elems/thread.
// Bit coverage (idx bits):
//   P1  : regs  H16  over bits 13..10   (j of load idx = j*1024 + t)
//   P2  : shfl  H32  over bits 4..0     (lane bits, sign-trick FFMA)
//   --- single smem exchange (XOR swizzle, conflict-free) ---
//   P3a : regs  H16  over bits 9..6     (j' of idx' = w_hi<<10 | j'<<6 | l4<<5 | w0<<4 | l_lo)
//   P3b : shfl  H2   over bit 5         (lane bit 4, mask 16)
// One __syncthreads() total.

#define N_ELEM 16384
#define THREADS 1024
#define REGS_PER 16

__device__ __forceinline__ int swz(int i) {
    // flip bit 4 based on bit 5: makes read pattern (l4->bit5) hit all 32 banks
    return i ^ (((i >> 5) & 1) << 4);
}

template <int N>
__device__ __forceinline__ void hadN(float* v) {
#pragma unroll
    for (int s = 1; s < N; s <<= 1) {
#pragma unroll
        for (int i = 0; i < N; i++) {
            if ((i & s) == 0) {
                float a = v[i];
                float b = v[i | s];
                v[i]     = a + b;
                v[i | s] = a - b;
            }
        }
    }
}

__global__ __launch_bounds__(THREADS, 2)
void fwht_kernel(const float* __restrict__ in, float* __restrict__ out) {
    extern __shared__ float sh[];
    const int t = threadIdx.x;
    const int l = t & 31;
    const int w = t >> 5;
    const size_t row = (size_t)blockIdx.x * N_ELEM;
    const float* __restrict__ pin = in + row;

    float v[REGS_PER];

    // ---- P1: load coalesced (idx = j*1024 + t), H16 over bits 13..10
#pragma unroll
    for (int j = 0; j < REGS_PER; j++) v[j] = pin[(j << 10) + t];
    hadN<REGS_PER>(v);

    // ---- P2: H32 over lane bits 4..0 via shfl_xor + sign-trick FFMA
#pragma unroll
    for (int m = 1; m <= 16; m <<= 1) {
        const float s = (l & m) ? -1.0f : 1.0f;
#pragma unroll
        for (int j = 0; j < REGS_PER; j++) {
            float p = __shfl_xor_sync(0xffffffffu, v[j], m);
            v[j] = fmaf(s, v[j], p);
        }
    }

    // ---- single exchange: write natural layout (swizzled)
#pragma unroll
    for (int j = 0; j < REGS_PER; j++) sh[swz((j << 10) + t)] = v[j];
    __syncthreads();

    // read: idx' = (w>>1)<<10 | j<<6 | (l>>4)<<5 | (w&1)<<4 | (l&15)
    const int base = ((w >> 1) << 10) | ((l >> 4) << 5) | ((w & 1) << 4) | (l & 15);
#pragma unroll
    for (int j = 0; j < REGS_PER; j++) v[j] = sh[swz(base + (j << 6))];

    // ---- P3a: H16 over bits 9..6 (reg index j)
    hadN<REGS_PER>(v);

    // ---- P3b: bit 5 lives on lane bit 4 -> one shfl stage, mask 16
    {
        const float s = (l & 16) ? -1.0f : 1.0f;
#pragma unroll
        for (int j = 0; j < REGS_PER; j++) {
            float p = __shfl_xor_sync(0xffffffffu, v[j], 16);
            v[j] = fmaf(s, v[j], p);
        }
    }

    // ---- scale by 2^-7 and store (per warp-op: two 64B segments, full sectors)
    float* __restrict__ pout = out + row;
#pragma unroll
    for (int j = 0; j < REGS_PER; j++)
        pout[base + (j << 6)] = v[j] * 0.0078125f;
}

extern "C" void kernel_launch(void* const* d_in, const int* in_sizes, int n_in,
                              void* d_out, int out_size) {
    const float* phi = (const float*)d_in[0];
    float* out = (float*)d_out;

    const size_t smem = N_ELEM * sizeof(float);  // 65536 B
    cudaFuncSetAttribute(fwht_kernel,
                         cudaFuncAttributeMaxDynamicSharedMemorySize,
                         (int)smem);

    const int batch = in_sizes[0] / N_ELEM;  // 4096
    fwht_kernel<<<batch, THREADS, smem>>>(phi, out);
}

// round 5
// speedup vs baseline: 1.2345x; 1.0753x over previous
#include <cuda_runtime.h>

// FWHT, 4096 rows x 16384 fp32. One CTA/row, 1024 threads, 16 elems/thread.
// Bit coverage:
//   P1: regs H16 over bits {13,12,1,0}   (float4 loads: i = j<<12 | t<<2 | k)
//   X1 exchange -> P2: regs H16 over bits {11,10,9,8}
//   X2 exchange (same-address writeback, no extra barrier) ->
//   P3: regs H16 over bits {7,6,5,4}
//   shfl stages over bits {3,2} (lane bits 3,2)
// 2 __syncthreads() total.
// Swizzle: phys(i) = i + 16*(i>>8)  (uniform 16-float pad per 256-float
// segment: injective, 16B-aligned, and all four smem patterns conflict-free;
// in particular the X2-read half-warps land on complementary 16-bank halves).

#define N_ELEM 16384
#define THREADS 1024
// max phys index = 16383 + 16*63 = 17391 -> round up
#define SMEM_FLOATS 17408

__device__ __forceinline__ int physz(int i) {
    return i + ((i >> 8) << 4);
}

template <int N>
__device__ __forceinline__ void hadN(float* v) {
#pragma unroll
    for (int s = 1; s < N; s <<= 1) {
#pragma unroll
        for (int i = 0; i < N; i++) {
            if ((i & s) == 0) {
                float a = v[i];
                float b = v[i | s];
                v[i]     = a + b;
                v[i | s] = a - b;
            }
        }
    }
}

__global__ __launch_bounds__(THREADS, 2)
void fwht_kernel(const float* __restrict__ in, float* __restrict__ out) {
    extern __shared__ float sh[];
    const int t = threadIdx.x;
    const int l = t & 31;
    const size_t row = (size_t)blockIdx.x * N_ELEM;

    float v[16];

    // ---- P1: float4 loads, i = j<<12 | t<<2 | k ; regs = (j,k) = bits {13,12,1,0}
    const float4* __restrict__ pin4 =
        reinterpret_cast<const float4*>(in + row + (t << 2));
#pragma unroll
    for (int j = 0; j < 4; j++) {
        float4 f = pin4[(size_t)j << 10];  // j*4096 floats
        v[4 * j + 0] = f.x;
        v[4 * j + 1] = f.y;
        v[4 * j + 2] = f.z;
        v[4 * j + 3] = f.w;
    }
    hadN<16>(v);  // butterflies bits 13,12,1,0

    // ---- X1 write: STS.128 at phys(j<<12 | t<<2)
#pragma unroll
    for (int j = 0; j < 4; j++) {
        const int i = (j << 12) | (t << 2);
        *reinterpret_cast<float4*>(&sh[physz(i)]) =
            make_float4(v[4 * j + 0], v[4 * j + 1], v[4 * j + 2], v[4 * j + 3]);
    }
    __syncthreads();

    // ---- X1 read: i = (t>>8)<<12 | r<<8 | (t&255) ; regs = bits {11..8}
    const int b1 = ((t >> 8) << 12) | (t & 255);
#pragma unroll
    for (int r = 0; r < 16; r++) v[r] = sh[physz(b1 | (r << 8))];
    hadN<16>(v);  // butterflies bits 11,10,9,8

    // ---- X2 write: SAME addresses this thread just read -> no WAR barrier
#pragma unroll
    for (int r = 0; r < 16; r++) sh[physz(b1 | (r << 8))] = v[r];
    __syncthreads();

    // ---- X2 read: i = (t>>4)<<8 | r<<4 | (t&15) ; regs = bits {7..4}
    const int b2 = ((t >> 4) << 8) | (t & 15);
#pragma unroll
    for (int r = 0; r < 16; r++) v[r] = sh[physz(b2 + (r << 4))];
    hadN<16>(v);  // butterflies bits 7,6,5,4

    // ---- bits 3,2 live on lane bits 3,2 -> two shfl stages
    {
        const float s3 = (l & 8) ? -1.0f : 1.0f;
#pragma unroll
        for (int r = 0; r < 16; r++) {
            float p = __shfl_xor_sync(0xffffffffu, v[r], 8);
            v[r] = fmaf(s3, v[r], p);
        }
        const float s2 = (l & 4) ? -1.0f : 1.0f;
#pragma unroll
        for (int r = 0; r < 16; r++) {
            float p = __shfl_xor_sync(0xffffffffu, v[r], 4);
            v[r] = fmaf(s2, v[r], p);
        }
    }

    // ---- scale 2^-7, store: per r two full 64B sectors per warp
    float* __restrict__ pout = out + row;
#pragma unroll
    for (int r = 0; r < 16; r++)
        pout[b2 + (r << 4)] = v[r] * 0.0078125f;
}

extern "C" void kernel_launch(void* const* d_in, const int* in_sizes, int n_in,
                              void* d_out, int out_size) {
    const float* phi = (const float*)d_in[0];
    float* out = (float*)d_out;

    const size_t smem = SMEM_FLOATS * sizeof(float);  // 69632 B
    cudaFuncSetAttribute(fwht_kernel,
                         cudaFuncAttributeMaxDynamicSharedMemorySize,
                         (int)smem);

    const int batch = in_sizes[0] / N_ELEM;  // 4096
    fwht_kernel<<<batch, THREADS, smem>>>(phi, out);
}

// round 6
// speedup vs baseline: 1.3250x; 1.0733x over previous
#include <cuda_runtime.h>

// FWHT, 4096 rows x 16384 fp32. Persistent CTAs: grid=148 (1/SM), 1024 thr,
// each CTA loops over rows stride-148 with register prefetch of the next row.
// Per-row dataflow (same as R5):
//   P1: regs H16 over bits {13,12,1,0}  (float4 LDG; vector lanes = bits 1,0)
//   X1 in smem -> P2: regs H16 over bits {11..8}  (same-address writeback)
//   X2        -> P3: regs H16 over bits {7..4}
//   shfl stages over bits {3,2}; scale; coalesced STG.
// Swizzle phys(i) = i + 16*(i>>8): injective, 16B-aligned, all smem patterns
// bank-conflict-free (X2-read half-warps hit complementary 16-bank halves).

#define N_ELEM 16384
#define THREADS 1024
#define SMEM_FLOATS 17408  // max phys index 16383 + 16*63 = 17391
#define NROWS 4096
#define GRID 148

__device__ __forceinline__ int physz(int i) { return i + ((i >> 8) << 4); }

template <int N>
__device__ __forceinline__ void hadN(float* v) {
#pragma unroll
    for (int s = 1; s < N; s <<= 1) {
#pragma unroll
        for (int i = 0; i < N; i++) {
            if ((i & s) == 0) {
                float a = v[i];
                float b = v[i | s];
                v[i]     = a + b;
                v[i | s] = a - b;
            }
        }
    }
}

__global__ __launch_bounds__(THREADS, 1)
void fwht_kernel(const float* __restrict__ in, float* __restrict__ out,
                 int nrows) {
    extern __shared__ float sh[];
    const int t = threadIdx.x;
    const int l = t & 31;

    // Immediate-foldable bases (all offsets per r are compile-time strides):
    // P1: phys(j<<12 | t<<2)        = pa  + j*4352
    // P2: phys((t>>8)<<12 | r<<8 | (t&255)) = pb1 + r*272
    // P3: phys((t>>4)<<8  | r<<4 | (t&15))  = pb2 + r*16
    const int pa  = (t << 2) + ((t >> 6) << 4);
    const int b1  = ((t >> 8) << 12) | (t & 255);
    const int pb1 = physz(b1);
    const int b2  = ((t >> 4) << 8) | (t & 15);
    const int pb2 = physz(b2);

    const float s3 = (l & 8) ? -1.0f : 1.0f;
    const float s2 = (l & 4) ? -1.0f : 1.0f;

    float v[16];

    // ---- prologue: load first row (raw)
    int row = blockIdx.x;
    {
        const float4* __restrict__ p4 =
            reinterpret_cast<const float4*>(in + (size_t)row * N_ELEM + (t << 2));
#pragma unroll
        for (int j = 0; j < 4; j++) {
            float4 f = p4[(size_t)j << 10];
            v[4 * j + 0] = f.x; v[4 * j + 1] = f.y;
            v[4 * j + 2] = f.z; v[4 * j + 3] = f.w;
        }
    }

    while (row < nrows) {
        const int nextrow = row + GRID;

        // ---- prefetch next row into vn (in flight during P1..P3)
        float vn[16];
        if (nextrow < nrows) {
            const float4* __restrict__ p4 =
                reinterpret_cast<const float4*>(in + (size_t)nextrow * N_ELEM + (t << 2));
#pragma unroll
            for (int j = 0; j < 4; j++) {
                float4 f = p4[(size_t)j << 10];
                vn[4 * j + 0] = f.x; vn[4 * j + 1] = f.y;
                vn[4 * j + 2] = f.z; vn[4 * j + 3] = f.w;
            }
        }

        // ---- P1: butterflies bits {13,12,1,0}; STS.128
        hadN<16>(v);
#pragma unroll
        for (int j = 0; j < 4; j++) {
            *reinterpret_cast<float4*>(&sh[pa + j * 4352]) =
                make_float4(v[4 * j + 0], v[4 * j + 1], v[4 * j + 2], v[4 * j + 3]);
        }
        __syncthreads();

        // ---- P2: bits {11..8}; in-place (same-address) writeback
#pragma unroll
        for (int r = 0; r < 16; r++) v[r] = sh[pb1 + r * 272];
        hadN<16>(v);
#pragma unroll
        for (int r = 0; r < 16; r++) sh[pb1 + r * 272] = v[r];
        __syncthreads();

        // ---- P3: bits {7..4}
#pragma unroll
        for (int r = 0; r < 16; r++) v[r] = sh[pb2 + r * 16];
        __syncthreads();  // smem buffer free for next iteration's P1 writes
        hadN<16>(v);

        // ---- bits {3,2} on lane bits 3,2 via shfl-xor sign trick
#pragma unroll
        for (int r = 0; r < 16; r++) {
            float p = __shfl_xor_sync(0xffffffffu, v[r], 8);
            v[r] = fmaf(s3, v[r], p);
        }
#pragma unroll
        for (int r = 0; r < 16; r++) {
            float p = __shfl_xor_sync(0xffffffffu, v[r], 4);
            v[r] = fmaf(s2, v[r], p);
        }

        // ---- scale 2^-7, coalesced store (full 64B sectors)
        float* __restrict__ pout = out + (size_t)row * N_ELEM;
#pragma unroll
        for (int r = 0; r < 16; r++)
            pout[b2 + (r << 4)] = v[r] * 0.0078125f;

        // ---- rotate pipeline
        row = nextrow;
#pragma unroll
        for (int k = 0; k < 16; k++) v[k] = vn[k];
    }
}

extern "C" void kernel_launch(void* const* d_in, const int* in_sizes, int n_in,
                              void* d_out, int out_size) {
    const float* phi = (const float*)d_in[0];
    float* out = (float*)d_out;

    const size_t smem = SMEM_FLOATS * sizeof(float);  // 69632 B
    cudaFuncSetAttribute(fwht_kernel,
                         cudaFuncAttributeMaxDynamicSharedMemorySize,
                         (int)smem);

    const int nrows = in_sizes[0] / N_ELEM;  // 4096
    const int grid = nrows < GRID ? nrows : GRID;
    fwht_kernel<<<grid, THREADS, smem>>>(phi, out, nrows);
}